// round 17
// baseline (speedup 1.0000x reference)
#include <cuda_runtime.h>
#include <cuda_fp16.h>
#include <mma.h>
#include <stdint.h>

using namespace nvcuda;

#define MAXN 100000
#define NPAD (MAXN + 64)
#define MAXE 1600000
#define IN_DIM 128
#define HC 128
#define OUT_DIM 32
#define HEADS 4
#define NEG_SLOPE 0.2f
#define EPS 1e-16f

#define LDA 136
#define LDB1 136
#define LDB2 40
#define GEMM1_SMEM (64*LDA*2 + 128*LDB1*2)   // 52224 B (>= 32KB fp32 out stage)
#define GEMM2_SMEM (64*LDA*2 + 128*LDB2*2)   // 27648 B (>= 8KB out stage)

// ---------------- scratch (device globals; zero-init at load) ----------------
__device__ float  g_h1f[NPAD * HC];        // h1 fp32 (gather payload)
__device__ __half g_agg1h[NPAD * HC];      // h1' fp16 (gemm2 input)
__device__ float  g_h2f[NPAD * OUT_DIM];   // h2 fp32 (gather payload)
__device__ __half g_W1h[IN_DIM * HC];      // fp16 W1
__device__ __half g_W2h[HC * OUT_DIM];     // fp16 W2
__device__ float g_asrc1[MAXN * HEADS];
__device__ float g_adst1[MAXN * HEADS];
__device__ float g_asrc2[MAXN];
__device__ float g_adst2[MAXN];
// CSR scratch (deg/cursor self-healing; btot[NB..127] stays 0 from load)
__device__ int g_deg[MAXN];
__device__ int g_rowptr[MAXN + 1];
__device__ int g_rowfin[MAXN];
__device__ int g_cursor[MAXN];
__device__ int g_esrc[MAXE + MAXN];
__device__ int g_btot[128];

// ---------------- #1: histogram + W1/W2 fp16 conversion -----------------------
__global__ void hist_kernel(const int* __restrict__ dst,
                            const float* __restrict__ W1,
                            const float* __restrict__ W2, int E, int EN) {
    int t = blockIdx.x * blockDim.x + threadIdx.x;
    if (t < 4096 + 1024) {
        float4 f;
        uint2* dp;
        if (t < 4096) {
            f = ((const float4*)W1)[t];
            dp = (uint2*)g_W1h + t;
        } else {
            f = ((const float4*)W2)[t - 4096];
            dp = (uint2*)g_W2h + (t - 4096);
        }
        half2 h0 = __floats2half2_rn(f.x, f.y);
        half2 h1 = __floats2half2_rn(f.z, f.w);
        uint2 p;
        p.x = *(uint32_t*)&h0;
        p.y = *(uint32_t*)&h1;
        *dp = p;
    }
    if (t >= EN) return;
    int d = (t < E) ? dst[t] : (t - E);
    atomicAdd(&g_deg[d], 1);
}

// ---------------- #2: per-block scan ------------------------------------------
__global__ void scan1_kernel(int N) {
    __shared__ int sh[1024];
    int i = blockIdx.x * 1024 + threadIdx.x;
    int v = (i < N) ? g_deg[i] : 0;
    if (i < N) g_deg[i] = 0;            // self-heal
    sh[threadIdx.x] = v;
    __syncthreads();
#pragma unroll
    for (int off = 1; off < 1024; off <<= 1) {
        int t = (threadIdx.x >= off) ? sh[threadIdx.x - off] : 0;
        __syncthreads();
        sh[threadIdx.x] += t;
        __syncthreads();
    }
    if (i < N) g_rowptr[i] = sh[threadIdx.x] - v;
    if (threadIdx.x == 1023) g_btot[blockIdx.x] = sh[1023];
}

// ---------------- #3: scatter (inline btot scan, atomic cursor) ---------------
__global__ void scatter_kernel(const int* __restrict__ src,
                               const int* __restrict__ dst, int E, int EN) {
    __shared__ int boff[128];
    if (threadIdx.x < 128) boff[threadIdx.x] = g_btot[threadIdx.x];
    __syncthreads();
    if (threadIdx.x < 128) {
        int v = boff[threadIdx.x];
        int acc = v;
#pragma unroll
        for (int off = 1; off < 128; off <<= 1) {
            int u = (threadIdx.x >= off) ? boff[threadIdx.x - off] : 0;
            __syncthreads();
            boff[threadIdx.x] = acc = acc + u;
            __syncthreads();
        }
        boff[threadIdx.x] = acc - v;
    } else {
#pragma unroll
        for (int off = 1; off < 128; off <<= 1) { __syncthreads(); __syncthreads(); }
    }
    __syncthreads();

    int t = blockIdx.x * blockDim.x + threadIdx.x;
    if (t >= EN) return;
    int s, d;
    if (t < E) { s = src[t]; d = dst[t]; }
    else       { s = t - E;  d = s; }
    int base = g_rowptr[d] + boff[d >> 10];
    g_rowfin[d] = base;
    int pos = base + atomicAdd(&g_cursor[d], 1);
    g_esrc[pos] = s;
}

// ---------------- #4: GEMM1 (fp16 WMMA, inline x convert, fp32 store) ---------
__global__ void gemm1_kernel(const float* __restrict__ x,
                             const float* __restrict__ att_s,
                             const float* __restrict__ att_d, int N) {
    extern __shared__ __half smh[];
    __half* As = smh;                   // 64 x LDA
    __half* Bs = smh + 64 * LDA;        // 128 x LDB1
    float* outs = (float*)smh;          // reused after MMA: 64*128 fp32 = 32KB
    int tid = threadIdx.x;
    int row0 = blockIdx.x * 64;

    {
        uint4* db = (uint4*)Bs;
        const uint4* sw = (const uint4*)g_W1h;
        for (int i = tid; i < 2048; i += 256) {
            int r = i >> 4, c = i & 15;
            db[r * 17 + c] = sw[i];
        }
    }
    {
        uint2* da = (uint2*)As;
        const float4* sx = (const float4*)x;
        for (int i = tid; i < 2048; i += 256) {
            int r = i >> 5, c4 = i & 31;
            int g = row0 + r;
            float4 f = (g < N) ? sx[(size_t)g * 32 + c4]
                               : make_float4(0.f, 0.f, 0.f, 0.f);
            half2 h0 = __floats2half2_rn(f.x, f.y);
            half2 h1 = __floats2half2_rn(f.z, f.w);
            uint2 p;
            p.x = *(uint32_t*)&h0;
            p.y = *(uint32_t*)&h1;
            da[r * 34 + c4] = p;
        }
    }
    __syncthreads();

    int w = tid >> 5;
    int lane = tid & 31;
    int wr = w >> 1, wc = w & 1;
    wmma::fragment<wmma::accumulator, 16, 16, 16, float> acc[4];
#pragma unroll
    for (int i = 0; i < 4; i++) wmma::fill_fragment(acc[i], 0.f);

#pragma unroll
    for (int k = 0; k < 8; k++) {
        wmma::fragment<wmma::matrix_a, 16, 16, 16, __half, wmma::row_major> a;
        wmma::load_matrix_sync(a, As + (wr * 16) * LDA + k * 16, LDA);
#pragma unroll
        for (int ct = 0; ct < 4; ct++) {
            wmma::fragment<wmma::matrix_b, 16, 16, 16, __half, wmma::row_major> b;
            wmma::load_matrix_sync(b, Bs + (k * 16) * LDB1 + wc * 64 + ct * 16, LDB1);
            wmma::mma_sync(acc[ct], a, b, acc[ct]);
        }
    }

    __syncthreads();
#pragma unroll
    for (int ct = 0; ct < 4; ct++)
        wmma::store_matrix_sync(outs + (wr * 16) * 128 + wc * 64 + ct * 16,
                                acc[ct], 128, wmma::mem_row_major);
    __syncthreads();

    // fp32 global store of h1
    {
        const float4* so = (const float4*)outs;
        float4* dh = (float4*)g_h1f;
        for (int i = tid; i < 64 * 32; i += 256) {
            int r = i >> 5, c4 = i & 31;
            int g = row0 + r;
            if (g < N) dh[(size_t)g * 32 + c4] = so[r * 32 + c4];
        }
    }

    // fused attn1
    float4 as = ((const float4*)att_s)[lane];
    float4 ad = ((const float4*)att_d)[lane];
#pragma unroll
    for (int r8 = 0; r8 < 8; r8++) {
        int r = w * 8 + r8;
        int g = row0 + r;
        float4 hv = ((const float4*)outs)[r * 32 + lane];
        float ps = hv.x * as.x + hv.y * as.y + hv.z * as.z + hv.w * as.w;
        float pd = hv.x * ad.x + hv.y * ad.y + hv.z * ad.z + hv.w * ad.w;
        ps += __shfl_xor_sync(0xFFFFFFFFu, ps, 1);
        pd += __shfl_xor_sync(0xFFFFFFFFu, pd, 1);
        ps += __shfl_xor_sync(0xFFFFFFFFu, ps, 2);
        pd += __shfl_xor_sync(0xFFFFFFFFu, pd, 2);
        ps += __shfl_xor_sync(0xFFFFFFFFu, ps, 4);
        pd += __shfl_xor_sync(0xFFFFFFFFu, pd, 4);
        if ((lane & 7) == 0 && g < N) {
            int h = lane >> 3;
            g_asrc1[g * 4 + h] = ps;
            g_adst1[g * 4 + h] = pd;
        }
    }
}

// ---------------- #5: layer-1 aggregation (staged exp, fp32 gather) -----------
// Chunk of 8 edges: lane l stages exp for edge (l>>2), head (l&3) — ONE
// gather+lrelu+expf warp-instruction per 8 edges. Inner loop shuffles ex
// from lane (j<<2)|h.
__global__ void agg1_kernel(const float* __restrict__ b1, int N, int EN) {
    int n = (blockIdx.x * blockDim.x + threadIdx.x) >> 5;
    int lane = threadIdx.x & 31;
    if (n >= N) return;
    if (lane == 0) g_cursor[n] = 0;     // self-heal
    int h  = lane >> 3;                 // accumulation head
    int hh = lane & 3;                  // staging head
    float adh = g_adst1[n * 4 + hh];
    int beg = g_rowfin[n];
    int end = (n + 1 < N) ? g_rowfin[n + 1] : EN;
    const float4* h4 = (const float4*)g_h1f;

    float4 acc = make_float4(0.f, 0.f, 0.f, 0.f);
    float den = 0.f;

    int full_end = beg + ((end - beg) & ~7);
    for (int base = beg; base < full_end; base += 8) {
        int sv = g_esrc[base + (lane >> 2)];
        float e = g_asrc1[sv * 4 + hh] + adh;
        e = (e > 0.f) ? e : NEG_SLOPE * e;
        float exv = __expf(e);
#pragma unroll
        for (int j = 0; j < 8; j++) {
            int s    = __shfl_sync(0xFFFFFFFFu, sv, j << 2);
            float ex = __shfl_sync(0xFFFFFFFFu, exv, (j << 2) | h);
            float4 v = h4[(size_t)s * 32 + lane];
            den += ex;
            acc.x += ex * v.x; acc.y += ex * v.y;
            acc.z += ex * v.z; acc.w += ex * v.w;
        }
    }
    if (full_end < end) {
        int eidx = full_end + (lane >> 2);
        int sv = (eidx < end) ? g_esrc[eidx] : 0;
        float e = g_asrc1[sv * 4 + hh] + adh;
        e = (e > 0.f) ? e : NEG_SLOPE * e;
        float exv = (eidx < end) ? __expf(e) : 0.f;
        int rem = end - full_end;
        for (int j = 0; j < rem; j++) {
            int s    = __shfl_sync(0xFFFFFFFFu, sv, j << 2);
            float ex = __shfl_sync(0xFFFFFFFFu, exv, (j << 2) | h);
            float4 v = h4[(size_t)s * 32 + lane];
            den += ex;
            acc.x += ex * v.x; acc.y += ex * v.y;
            acc.z += ex * v.z; acc.w += ex * v.w;
        }
    }
    float inv = 1.f / (den + EPS);
    float4 bias = ((const float4*)b1)[lane];
    float rx = fmaxf(acc.x * inv + bias.x, 0.f);
    float ry = fmaxf(acc.y * inv + bias.y, 0.f);
    float rz = fmaxf(acc.z * inv + bias.z, 0.f);
    float rw = fmaxf(acc.w * inv + bias.w, 0.f);
    half2 h0 = __floats2half2_rn(rx, ry);
    half2 h1 = __floats2half2_rn(rz, rw);
    uint2 p;
    p.x = *(uint32_t*)&h0;
    p.y = *(uint32_t*)&h1;
    ((uint2*)g_agg1h)[n * 32 + lane] = p;
}

// ---------------- #6: GEMM2 (fp16 WMMA, fp32 store) + attn2 -------------------
__global__ void gemm2_kernel(const float* __restrict__ att_s,
                             const float* __restrict__ att_d, int N) {
    extern __shared__ __half smh[];
    __half* As = smh;                   // 64 x LDA
    __half* Bs = smh + 64 * LDA;        // 128 x LDB2
    float* outs = (float*)smh;          // reused: 64*32 fp32 = 8KB
    int tid = threadIdx.x;
    int lane = tid & 31;
    int row0 = blockIdx.x * 64;

    {
        uint4* db = (uint4*)Bs;
        const uint4* sw = (const uint4*)g_W2h;
        for (int i = tid; i < 512; i += 256) {
            int r = i >> 2, c = i & 3;
            db[r * 5 + c] = sw[i];
        }
    }
    {
        uint4* da = (uint4*)As;
        const uint4* sa = (const uint4*)g_agg1h;
        uint4 z = make_uint4(0u, 0u, 0u, 0u);
        for (int i = tid; i < 1024; i += 256) {
            int r = i >> 4, c = i & 15;
            int g = row0 + r;
            da[r * 17 + c] = (g < N) ? sa[(size_t)g * 16 + c] : z;
        }
    }
    __syncthreads();

    int w = tid >> 5;
    int wr = w & 3, wc = w >> 2;
    wmma::fragment<wmma::accumulator, 16, 16, 16, float> acc;
    wmma::fill_fragment(acc, 0.f);

#pragma unroll
    for (int k = 0; k < 8; k++) {
        wmma::fragment<wmma::matrix_a, 16, 16, 16, __half, wmma::row_major> a;
        wmma::fragment<wmma::matrix_b, 16, 16, 16, __half, wmma::row_major> b;
        wmma::load_matrix_sync(a, As + (wr * 16) * LDA + k * 16, LDA);
        wmma::load_matrix_sync(b, Bs + (k * 16) * LDB2 + wc * 16, LDB2);
        wmma::mma_sync(acc, a, b, acc);
    }

    __syncthreads();
    wmma::store_matrix_sync(outs + (wr * 16) * 32 + wc * 16, acc, 32, wmma::mem_row_major);
    __syncthreads();

    // fp32 global store of h2
    {
        const float4* so = (const float4*)outs;
        float4* dh = (float4*)g_h2f;
        for (int i = tid; i < 64 * 8; i += 256) {
            int r = i >> 3, c4 = i & 7;
            int g = row0 + r;
            if (g < N) dh[(size_t)g * 8 + c4] = so[r * 8 + c4];
        }
    }

    float asv = att_s[lane];
    float adv = att_d[lane];
#pragma unroll
    for (int r8 = 0; r8 < 8; r8++) {
        int r = w * 8 + r8;
        int g = row0 + r;
        float hv = outs[r * 32 + lane];
        float ps = hv * asv;
        float pd = hv * adv;
#pragma unroll
        for (int o = 16; o > 0; o >>= 1) {
            ps += __shfl_xor_sync(0xFFFFFFFFu, ps, o);
            pd += __shfl_xor_sync(0xFFFFFFFFu, pd, o);
        }
        if (lane == 0 && g < N) {
            g_asrc2[g] = ps;
            g_adst2[g] = pd;
        }
    }
}

// ---------------- #7: layer-2 aggregation (staged exp, fp32 gather) -----------
// Chunk of 16 edges: lane l stages exp for edge (l&15); inner shuffles.
__global__ void agg2_kernel(float* __restrict__ out,
                            const float* __restrict__ b2, int N, int EN) {
    int n = (blockIdx.x * blockDim.x + threadIdx.x) >> 5;
    int lane = threadIdx.x & 31;
    if (n >= N) return;
    float ad = g_adst2[n];
    int beg = g_rowfin[n];
    int end = (n + 1 < N) ? g_rowfin[n + 1] : EN;

    float acc = 0.f;
    float den = 0.f;
    int full_end = beg + ((end - beg) & ~15);
    for (int base = beg; base < full_end; base += 16) {
        int sv = g_esrc[base + (lane & 15)];
        float e = g_asrc2[sv] + ad;
        e = (e > 0.f) ? e : NEG_SLOPE * e;
        float exv = __expf(e);
#pragma unroll
        for (int j = 0; j < 16; j++) {
            int s    = __shfl_sync(0xFFFFFFFFu, sv, j);
            float ex = __shfl_sync(0xFFFFFFFFu, exv, j);
            den += ex;
            acc += ex * g_h2f[(size_t)s * 32 + lane];
        }
    }
    if (full_end < end) {
        int eidx = full_end + (lane & 15);
        int sv = (eidx < end) ? g_esrc[eidx] : 0;
        float e = g_asrc2[sv] + ad;
        e = (e > 0.f) ? e : NEG_SLOPE * e;
        float exv = (eidx < end) ? __expf(e) : 0.f;
        int rem = end - full_end;
        for (int j = 0; j < rem; j++) {
            int s    = __shfl_sync(0xFFFFFFFFu, sv, j);
            float ex = __shfl_sync(0xFFFFFFFFu, exv, j);
            den += ex;
            acc += ex * g_h2f[(size_t)s * 32 + lane];
        }
    }
    out[n * 32 + lane] = acc / (den + EPS) + b2[lane];
}

// ---------------- launch ------------------------------------------------------
extern "C" void kernel_launch(void* const* d_in, const int* in_sizes, int n_in,
                              void* d_out, int out_size) {
    const float* x      = (const float*)d_in[0];
    const int*   ei     = (const int*)  d_in[1];
    const float* W1     = (const float*)d_in[2];
    const float* att_s1 = (const float*)d_in[3];
    const float* att_d1 = (const float*)d_in[4];
    const float* b1     = (const float*)d_in[5];
    const float* W2     = (const float*)d_in[6];
    const float* att_s2 = (const float*)d_in[7];
    const float* att_d2 = (const float*)d_in[8];
    const float* b2     = (const float*)d_in[9];

    int N = in_sizes[0] / IN_DIM;
    int E = in_sizes[1] / 2;
    const int* src = ei;
    const int* dst = ei + E;
    float* out = (float*)d_out;
    int EN = E + N;
    int NB = (N + 1023) / 1024;

    static bool init_done = false;
    if (!init_done) {
        cudaFuncSetAttribute(gemm1_kernel, cudaFuncAttributeMaxDynamicSharedMemorySize, GEMM1_SMEM);
        cudaFuncSetAttribute(gemm2_kernel, cudaFuncAttributeMaxDynamicSharedMemorySize, GEMM2_SMEM);
        init_done = true;
    }

    // #1..#3: CSR build (+W conversion folded into #1)
    hist_kernel<<<(EN + 255) / 256, 256>>>(dst, W1, W2, E, EN);
    scan1_kernel<<<NB, 1024>>>(N);
    scatter_kernel<<<(EN + 255) / 256, 256>>>(src, dst, E, EN);

    // #4: gemm1 (inline x convert, fp32 h1 store)
    gemm1_kernel<<<(N + 63) / 64, 256, GEMM1_SMEM>>>(x, att_s1, att_d1, N);
    // #5: agg1 (staged exp)
    agg1_kernel<<<(N * 32 + 255) / 256, 256>>>(b1, N, EN);
    // #6, #7: layer 2
    gemm2_kernel<<<(N + 63) / 64, 256, GEMM2_SMEM>>>(att_s2, att_d2, N);
    agg2_kernel<<<(N * 32 + 255) / 256, 256>>>(out, b2, N, EN);
}